// round 2
// baseline (speedup 1.0000x reference)
#include <cuda_runtime.h>
#include <cuda_bf16.h>
#include <cstdint>

// ---------------------------------------------------------------------------
// Problem constants
// ---------------------------------------------------------------------------
#define M_ROWS 8192   // 4*2048 samples
#define NF     4096   // output features (M_PAD)
#define KF     4096   // input features (N_PAD)

// ---------------------------------------------------------------------------
// Scratch (device globals — no allocation allowed)
// ---------------------------------------------------------------------------
__device__ __nv_bfloat16 g_Xhi[(size_t)M_ROWS * KF];
__device__ __nv_bfloat16 g_Xlo[(size_t)M_ROWS * KF];
__device__ __nv_bfloat16 g_Whi[(size_t)NF * KF];
__device__ __nv_bfloat16 g_Wlo[(size_t)NF * KF];
__device__ float         g_Yr [(size_t)M_ROWS * NF];

// ---------------------------------------------------------------------------
// Helpers
// ---------------------------------------------------------------------------
__device__ __forceinline__ void fht64(float* v) {
#pragma unroll
    for (int h = 1; h < 64; h <<= 1) {
#pragma unroll
        for (int i = 0; i < 64; i += 2 * h) {
#pragma unroll
            for (int j = i; j < i + h; j++) {
                float a = v[j], b = v[j + h];
                v[j] = a + b;
                v[j + h] = a - b;
            }
        }
    }
}

__device__ __forceinline__ void cp_async16(uint32_t dst_smem, const void* src) {
    asm volatile("cp.async.cg.shared.global [%0], [%1], 16;\n" :: "r"(dst_smem), "l"(src));
}
__device__ __forceinline__ void cp_commit() {
    asm volatile("cp.async.commit_group;\n");
}
template <int N>
__device__ __forceinline__ void cp_wait() {
    asm volatile("cp.async.wait_group %0;\n" :: "n"(N));
}

__device__ __forceinline__ void ldmx4(uint32_t* r, uint32_t addr) {
    asm volatile("ldmatrix.sync.aligned.m8n8.x4.shared.b16 {%0,%1,%2,%3}, [%4];\n"
                 : "=r"(r[0]), "=r"(r[1]), "=r"(r[2]), "=r"(r[3])
                 : "r"(addr));
}

__device__ __forceinline__ void mma_bf16(float* c, const uint32_t* a, uint32_t b0, uint32_t b1) {
    asm volatile(
        "mma.sync.aligned.m16n8k16.row.col.f32.bf16.bf16.f32 "
        "{%0,%1,%2,%3}, {%4,%5,%6,%7}, {%8,%9}, {%0,%1,%2,%3};\n"
        : "+f"(c[0]), "+f"(c[1]), "+f"(c[2]), "+f"(c[3])
        : "r"(a[0]), "r"(a[1]), "r"(a[2]), "r"(a[3]), "r"(b0), "r"(b1));
}

// ---------------------------------------------------------------------------
// Kernel A: x_rht = FHT(x * SV) -> bf16 hi/lo
// One row per 64-thread block. 4096 = 64x64 tensor decomposition:
// register FHT64 over low bits, transpose via padded smem, FHT64 over high bits.
// ---------------------------------------------------------------------------
__global__ void fht_x_kernel(const float* __restrict__ x, const float* __restrict__ SV) {
    __shared__ float s[64 * 65];
    const int row = blockIdx.x;
    const int t = threadIdx.x;
    const float* xr = x + (size_t)row * KF;

    // Coalesced load with SV sign flip
    for (int i = t; i < 4096; i += 64)
        s[(i >> 6) * 65 + (i & 63)] = xr[i] * SV[i];
    __syncthreads();

    float v[64];
    // First pass: FHT over low 6 bits (thread t owns u = t)
#pragma unroll
    for (int j = 0; j < 64; j++) v[j] = s[t * 65 + j];
    fht64(v);
#pragma unroll
    for (int j = 0; j < 64; j++) s[t * 65 + j] = v[j];
    __syncthreads();

    // Second pass: FHT over high 6 bits (thread t owns v = t)
#pragma unroll
    for (int u = 0; u < 64; u++) v[u] = s[u * 65 + t];
    fht64(v);
#pragma unroll
    for (int u = 0; u < 64; u++) s[u * 65 + t] = v[u] * (1.0f / 64.0f);
    __syncthreads();

    // Coalesced store: bf16 hi/lo split
    for (int i = t; i < 4096; i += 64) {
        float val = s[(i >> 6) * 65 + (i & 63)];
        __nv_bfloat16 hi = __float2bfloat16(val);
        __nv_bfloat16 lo = __float2bfloat16(val - __bfloat162float(hi));
        g_Xhi[(size_t)row * KF + i] = hi;
        g_Xlo[(size_t)row * KF + i] = lo;
    }
}

// ---------------------------------------------------------------------------
// Kernel B: W dequant -> bf16 hi/lo.  One thread per (m, g) group of 8.
// ---------------------------------------------------------------------------
__global__ void dequant_kernel(const int* __restrict__ Qidxs, const float* __restrict__ cb) {
    const int tid = blockIdx.x * blockDim.x + threadIdx.x;  // m*512 + g
    if (tid >= NF * (KF / 8)) return;
    const int idx = Qidxs[tid];
    const float4 c0 = reinterpret_cast<const float4*>(cb)[idx * 2];
    const float4 c1 = reinterpret_cast<const float4*>(cb)[idx * 2 + 1];
    float f[8] = {c0.x, c0.y, c0.z, c0.w, c1.x, c1.y, c1.z, c1.w};
    union { unsigned short us[8]; uint4 v; } H, L;
#pragma unroll
    for (int j = 0; j < 8; j++) {
        __nv_bfloat16 h = __float2bfloat16(f[j]);
        __nv_bfloat16 l = __float2bfloat16(f[j] - __bfloat162float(h));
        H.us[j] = __bfloat16_as_ushort(h);
        L.us[j] = __bfloat16_as_ushort(l);
    }
    reinterpret_cast<uint4*>(g_Whi)[tid] = H.v;
    reinterpret_cast<uint4*>(g_Wlo)[tid] = L.v;
}

// ---------------------------------------------------------------------------
// Kernel C: GEMM  Yr[M, N] = Xrht[M, K] @ W[N, K]^T  (3-pass bf16 split)
// 128x128 block tile, BK=32, 8 warps (2x4), 64x32 warp tile,
// double-buffered cp.async, ldmatrix, mma.sync m16n8k16 bf16.
// ---------------------------------------------------------------------------
#define GEMM_STG_ELEMS 20480          // 4 tiles * 128 rows * 40 elems
#define GEMM_SMEM_BYTES (2 * GEMM_STG_ELEMS * 2)

__global__ __launch_bounds__(256, 1) void gemm_kernel(const float* __restrict__ wsp) {
    extern __shared__ __nv_bfloat16 sm[];
    const int tid = threadIdx.x;
    const int lane = tid & 31, warp = tid >> 5;
    const int wm = warp & 1, wn = warp >> 1;  // 2 x 4 warp grid

    // block swizzle for L2 reuse: groups of 8 M-blocks per N sweep
    const int NUMN = NF / 128;           // 32
    const int GM = 8;
    const int per = GM * NUMN;           // 256
    const int grp = blockIdx.x / per, rem = blockIdx.x % per;
    const int bm = grp * GM + (rem & (GM - 1));
    const int bn = rem / GM;

    const uint32_t sbase = (uint32_t)__cvta_generic_to_shared(sm);

    float acc[4][4][4];
#pragma unroll
    for (int a = 0; a < 4; a++)
#pragma unroll
        for (int b = 0; b < 4; b++)
#pragma unroll
            for (int c = 0; c < 4; c++) acc[a][b][c] = 0.0f;

    // stage tile element offsets: Ahi +0, Alo +5120, Bhi +10240, Blo +15360
    auto load_stage = [&](int st, int kt) {
        const int k0 = kt * 32;
#pragma unroll
        for (int t = 0; t < 2; t++) {
            const int chunk = tid + t * 256;      // 512 chunks of 16B per tile
            const int r = chunk >> 2;
            const int c8 = (chunk & 3) << 3;      // element col
            const size_t ga = (size_t)(bm * 128 + r) * KF + k0 + c8;
            const size_t gb = (size_t)(bn * 128 + r) * KF + k0 + c8;
            const uint32_t da = sbase + (uint32_t)(st * GEMM_STG_ELEMS + r * 40 + c8) * 2;
            cp_async16(da,             g_Xhi + ga);
            cp_async16(da +  5120 * 2, g_Xlo + ga);
            cp_async16(da + 10240 * 2, g_Whi + gb);
            cp_async16(da + 15360 * 2, g_Wlo + gb);
        }
    };

    const int KT = KF / 32;  // 128
    load_stage(0, 0);
    cp_commit();

    for (int kt = 0; kt < KT; kt++) {
        if (kt + 1 < KT) load_stage((kt + 1) & 1, kt + 1);
        cp_commit();
        cp_wait<1>();
        __syncthreads();

        const int aoff = (kt & 1) * GEMM_STG_ELEMS;
#pragma unroll
        for (int kk = 0; kk < 32; kk += 16) {
            uint32_t Ah[4][4], Al[4][4];
#pragma unroll
            for (int mt = 0; mt < 4; mt++) {
                const int row = wm * 64 + mt * 16 + (lane & 15);
                const int col = kk + ((lane >> 4) << 3);
                const uint32_t ad = sbase + (uint32_t)(aoff + row * 40 + col) * 2;
                ldmx4(Ah[mt], ad);
                ldmx4(Al[mt], ad + 5120 * 2);
            }
            uint32_t Bh[2][4], Bl[2][4];
#pragma unroll
            for (int nt = 0; nt < 2; nt++) {
                const int nrow = wn * 32 + nt * 16 + ((lane >> 4) << 3) + (lane & 7);
                const int kcol = kk + (((lane >> 3) & 1) << 3);
                const uint32_t bd = sbase + (uint32_t)(aoff + 10240 + nrow * 40 + kcol) * 2;
                ldmx4(Bh[nt], bd);
                ldmx4(Bl[nt], bd + 5120 * 2);
            }
#pragma unroll
            for (int mt = 0; mt < 4; mt++) {
#pragma unroll
                for (int nn = 0; nn < 4; nn++) {
                    const int nt = nn >> 1;
                    const int p = (nn & 1) * 2;
                    mma_bf16(acc[mt][nn], Ah[mt], Bh[nt][p], Bh[nt][p + 1]);
                    mma_bf16(acc[mt][nn], Ah[mt], Bl[nt][p], Bl[nt][p + 1]);
                    mma_bf16(acc[mt][nn], Al[mt], Bh[nt][p], Bh[nt][p + 1]);
                }
            }
        }
        __syncthreads();
    }

    // epilogue
    const float ws = *wsp;
    const int gm0 = bm * 128 + wm * 64;
    const int gn0 = bn * 128 + wn * 32;
#pragma unroll
    for (int mt = 0; mt < 4; mt++) {
#pragma unroll
        for (int nn = 0; nn < 4; nn++) {
            const int r0 = gm0 + mt * 16 + (lane >> 2);
            const int c0 = gn0 + nn * 8 + (lane & 3) * 2;
            float2 v0 = make_float2(acc[mt][nn][0] * ws, acc[mt][nn][1] * ws);
            float2 v1 = make_float2(acc[mt][nn][2] * ws, acc[mt][nn][3] * ws);
            *reinterpret_cast<float2*>(&g_Yr[(size_t)r0 * NF + c0]) = v0;
            *reinterpret_cast<float2*>(&g_Yr[(size_t)(r0 + 8) * NF + c0]) = v1;
        }
    }
}

// ---------------------------------------------------------------------------
// Kernel D: y = FHT(y_rht) * SU   -> fp32 output
// ---------------------------------------------------------------------------
__global__ void fht_y_kernel(const float* __restrict__ SU, float* __restrict__ out) {
    __shared__ float s[64 * 65];
    const int row = blockIdx.x;
    const int t = threadIdx.x;
    const float* yr = g_Yr + (size_t)row * NF;

    for (int i = t; i < 4096; i += 64)
        s[(i >> 6) * 65 + (i & 63)] = yr[i];
    __syncthreads();

    float v[64];
#pragma unroll
    for (int j = 0; j < 64; j++) v[j] = s[t * 65 + j];
    fht64(v);
#pragma unroll
    for (int j = 0; j < 64; j++) s[t * 65 + j] = v[j];
    __syncthreads();

#pragma unroll
    for (int u = 0; u < 64; u++) v[u] = s[u * 65 + t];
    fht64(v);
#pragma unroll
    for (int u = 0; u < 64; u++) s[u * 65 + t] = v[u] * (1.0f / 64.0f);
    __syncthreads();

    for (int i = t; i < 4096; i += 64)
        out[(size_t)row * NF + i] = s[(i >> 6) * 65 + (i & 63)] * SU[i];
}

// ---------------------------------------------------------------------------
// Launch
// ---------------------------------------------------------------------------
extern "C" void kernel_launch(void* const* d_in, const int* in_sizes, int n_in,
                              void* d_out, int out_size) {
    const float* x      = (const float*)d_in[0];
    const int*   Qidxs  = (const int*)  d_in[1];
    const float* SU     = (const float*)d_in[2];
    const float* SV     = (const float*)d_in[3];
    const float* Wscale = (const float*)d_in[4];
    const float* cb     = (const float*)d_in[5];
    float* out = (float*)d_out;

    fht_x_kernel<<<M_ROWS, 64>>>(x, SV);
    dequant_kernel<<<(NF * (KF / 8)) / 256, 256>>>(Qidxs, cb);

    cudaFuncSetAttribute(gemm_kernel, cudaFuncAttributeMaxDynamicSharedMemorySize,
                         GEMM_SMEM_BYTES);
    gemm_kernel<<<(M_ROWS / 128) * (NF / 128), 256, GEMM_SMEM_BYTES>>>(Wscale);

    fht_y_kernel<<<M_ROWS, 64>>>(SU, out);
}

// round 5
// speedup vs baseline: 1.9162x; 1.9162x over previous
#include <cuda_runtime.h>
#include <cuda_fp16.h>
#include <cstdint>

// ---------------------------------------------------------------------------
// Problem constants
// ---------------------------------------------------------------------------
#define M_ROWS 8192   // 4*2048 samples
#define NF     4096   // output features
#define KF     4096   // input features

// ---------------------------------------------------------------------------
// Scratch (device globals — no allocation allowed)
// ---------------------------------------------------------------------------
__device__ __half g_Xh[(size_t)M_ROWS * KF];   // x_rht? no: raw x in fp16
__device__ float  g_Wt[(size_t)NF * KF];       // H*W*H intermediate (f32)
__device__ __half g_Wh[(size_t)NF * KF];       // Weff hi (fp16)
__device__ __half g_Wl[(size_t)NF * KF];       // Weff lo (fp16)

// ---------------------------------------------------------------------------
// Helpers
// ---------------------------------------------------------------------------
__device__ __forceinline__ void fht64(float* v) {
#pragma unroll
    for (int h = 1; h < 64; h <<= 1) {
#pragma unroll
        for (int i = 0; i < 64; i += 2 * h) {
#pragma unroll
            for (int j = i; j < i + h; j++) {
                float a = v[j], b = v[j + h];
                v[j] = a + b;
                v[j + h] = a - b;
            }
        }
    }
}

__device__ __forceinline__ void cp_async16(uint32_t dst_smem, const void* src) {
    asm volatile("cp.async.cg.shared.global [%0], [%1], 16;\n" :: "r"(dst_smem), "l"(src));
}
__device__ __forceinline__ void cp_commit() {
    asm volatile("cp.async.commit_group;\n");
}
template <int N>
__device__ __forceinline__ void cp_wait() {
    asm volatile("cp.async.wait_group %0;\n" :: "n"(N));
}

__device__ __forceinline__ void ldmx4(uint32_t* r, uint32_t addr) {
    asm volatile("ldmatrix.sync.aligned.m8n8.x4.shared.b16 {%0,%1,%2,%3}, [%4];\n"
                 : "=r"(r[0]), "=r"(r[1]), "=r"(r[2]), "=r"(r[3])
                 : "r"(addr));
}

__device__ __forceinline__ void mma_fp16(float* c, const uint32_t* a, uint32_t b0, uint32_t b1) {
    asm volatile(
        "mma.sync.aligned.m16n8k16.row.col.f32.f16.f16.f32 "
        "{%0,%1,%2,%3}, {%4,%5,%6,%7}, {%8,%9}, {%0,%1,%2,%3};\n"
        : "+f"(c[0]), "+f"(c[1]), "+f"(c[2]), "+f"(c[3])
        : "r"(a[0]), "r"(a[1]), "r"(a[2]), "r"(a[3]), "r"(b0), "r"(b1));
}

// ---------------------------------------------------------------------------
// Kernel 1: x -> fp16 (elementwise convert; FHTs are folded into W)
// ---------------------------------------------------------------------------
__global__ void conv_x(const float* __restrict__ x) {
    const size_t i = ((size_t)blockIdx.x * 256 + threadIdx.x) * 8;
    const float4 a = *reinterpret_cast<const float4*>(x + i);
    const float4 b = *reinterpret_cast<const float4*>(x + i + 4);
    __half2 h0 = __floats2half2_rn(a.x, a.y);
    __half2 h1 = __floats2half2_rn(a.z, a.w);
    __half2 h2 = __floats2half2_rn(b.x, b.y);
    __half2 h3 = __floats2half2_rn(b.z, b.w);
    uint4 pack;
    pack.x = *reinterpret_cast<uint32_t*>(&h0);
    pack.y = *reinterpret_cast<uint32_t*>(&h1);
    pack.z = *reinterpret_cast<uint32_t*>(&h2);
    pack.w = *reinterpret_cast<uint32_t*>(&h3);
    *reinterpret_cast<uint4*>(&g_Xh[i]) = pack;
}

// ---------------------------------------------------------------------------
// Kernel 2: dequant + row-FHT (over k) + SV[k]*Wscale  -> g_Wt (f32)
// 2 rows per 128-thread block; 64x64 tensor decomposition in smem.
// ---------------------------------------------------------------------------
__global__ void dequant_fht_row(const int* __restrict__ Q, const float* __restrict__ cb,
                                const float* __restrict__ SV, const float* __restrict__ wsp) {
    __shared__ float s[2][64 * 65];
    const int half_id = threadIdx.x >> 6;
    const int t = threadIdx.x & 63;
    const int n = blockIdx.x * 2 + half_id;
    float* sm = s[half_id];
    const int* q = Q + (size_t)n * 512;

    for (int i = t; i < 4096; i += 64) {
        const int idx = q[i >> 3];
        sm[(i >> 6) * 65 + (i & 63)] = cb[idx * 8 + (i & 7)];
    }
    __syncthreads();

    float v[64];
#pragma unroll
    for (int j = 0; j < 64; j++) v[j] = sm[t * 65 + j];
    fht64(v);
#pragma unroll
    for (int j = 0; j < 64; j++) sm[t * 65 + j] = v[j];
    __syncthreads();

#pragma unroll
    for (int u = 0; u < 64; u++) v[u] = sm[u * 65 + t];
    fht64(v);
#pragma unroll
    for (int u = 0; u < 64; u++) sm[u * 65 + t] = v[u] * (1.0f / 64.0f);
    __syncthreads();

    const float ws = *wsp;
    for (int i = t; i < 4096; i += 64)
        g_Wt[(size_t)n * KF + i] = sm[(i >> 6) * 65 + (i & 63)] * SV[i] * ws;
}

// ---------------------------------------------------------------------------
// Kernel 3: column-FHT pass 1 (over low 6 bits of n), in place on g_Wt.
// Thread owns one k-column; per-r accesses are fully coalesced (512B/row).
// ---------------------------------------------------------------------------
__global__ void fht_col1() {
    const int k = blockIdx.x * 256 + threadIdx.x;
    float* base = g_Wt + (size_t)(blockIdx.y * 64) * KF + k;
    float v[64];
#pragma unroll
    for (int r = 0; r < 64; r++) v[r] = base[(size_t)r * KF];
    fht64(v);
#pragma unroll
    for (int r = 0; r < 64; r++) base[(size_t)r * KF] = v[r];
}

// ---------------------------------------------------------------------------
// Kernel 4: column-FHT pass 2 (over high 6 bits of n) + 1/64 norm + SU[n],
// then split to fp16 hi/lo -> g_Wh, g_Wl.
// ---------------------------------------------------------------------------
__global__ void fht_col2(const float* __restrict__ SU) {
    const int k = blockIdx.x * 256 + threadIdx.x;
    const int b = blockIdx.y;
    const float* src = g_Wt + (size_t)b * KF + k;
    float v[64];
#pragma unroll
    for (int r = 0; r < 64; r++) v[r] = src[(size_t)r * 64 * KF];
    fht64(v);
#pragma unroll
    for (int r = 0; r < 64; r++) {
        const int n = b + 64 * r;
        const float val = v[r] * (1.0f / 64.0f) * SU[n];
        const __half h = __float2half_rn(val);
        const __half l = __float2half_rn(val - __half2float(h));
        const size_t o = (size_t)n * KF + k;
        g_Wh[o] = h;
        g_Wl[o] = l;
    }
}

// ---------------------------------------------------------------------------
// Kernel 5: GEMM  out[M, N] = Xh[M, K] @ (Wh + Wl)[N, K]^T  (2-pass fp16)
// 128x128 tile, BK=64, 4-stage cp.async pipeline, XOR-swizzled 128B rows,
// 8 warps (2x4), warp tile 64x32, mma.sync m16n8k16 fp16/f32.
// ---------------------------------------------------------------------------
#define BM 128
#define BN 128
#define BK 64
#define STAGES 4
#define TILE_B 16384                  // one 128x64 fp16 tile = 16 KB
#define STG (3 * TILE_B)              // A + Bh + Bl = 48 KB
#define GEMM_DSMEM (STAGES * STG)     // 192 KB

__global__ __launch_bounds__(256, 1) void gemm_hmma(float* __restrict__ out) {
    extern __shared__ char dyn[];
    const int tid = threadIdx.x;
    const int lane = tid & 31, warp = tid >> 5;
    const int wm = warp & 1, wn = warp >> 1;  // 2 x 4 warp grid

    // block swizzle for L2 reuse: groups of 8 bm-blocks per bn sweep
    const int GM = 8;
    const int NUMN = NF / BN;            // 32
    const int per = GM * NUMN;           // 256
    const int grp = blockIdx.x / per, rem = blockIdx.x % per;
    const int bm = grp * GM + (rem & (GM - 1));
    const int bn = rem / GM;

    const uint32_t sbase = (uint32_t)__cvta_generic_to_shared(dyn);

    float acc[4][4][4];
#pragma unroll
    for (int a = 0; a < 4; a++)
#pragma unroll
        for (int b = 0; b < 4; b++)
#pragma unroll
            for (int c = 0; c < 4; c++) acc[a][b][c] = 0.0f;

    // stage fill: 1024 16B chunks per tile; swizzle: row r, chunk j ->
    // off = r*128 + ((j ^ (r&7)) << 4)
    auto load_stage = [&](int st, int c) {
        const uint32_t sb = sbase + st * STG;
        const int k0 = c * BK;
#pragma unroll
        for (int i = 0; i < 4; i++) {
            const int id = tid + i * 256;
            const int r = id >> 3, j = id & 7;
            const uint32_t off = r * 128 + ((j ^ (r & 7)) << 4);
            const size_t ga = (size_t)(bm * BM + r) * KF + k0 + j * 8;
            const size_t gb = (size_t)(bn * BN + r) * KF + k0 + j * 8;
            cp_async16(sb + off,              g_Xh + ga);
            cp_async16(sb + TILE_B + off,     g_Wh + gb);
            cp_async16(sb + 2 * TILE_B + off, g_Wl + gb);
        }
        cp_commit();
    };

    const int NCH = KF / BK;  // 64
    load_stage(0, 0);
    load_stage(1, 1);
    load_stage(2, 2);

    for (int c = 0; c < NCH; c++) {
        if (c <= NCH - 3)      cp_wait<2>();
        else if (c == NCH - 2) cp_wait<1>();
        else                   cp_wait<0>();
        __syncthreads();

        if (c + 3 < NCH) load_stage((c + 3) & 3, c + 3);

        const uint32_t sb = sbase + (c & 3) * STG;
#pragma unroll
        for (int kk = 0; kk < 4; kk++) {
            const int k0 = kk * 16;
            uint32_t Af[4][4];
#pragma unroll
            for (int mt = 0; mt < 4; mt++) {
                const int row = wm * 64 + mt * 16 + (lane & 15);
                const int ce = k0 + ((lane >> 4) << 3);       // element col
                const int j = ce >> 3;
                const uint32_t ad = sb + row * 128 + ((j ^ (row & 7)) << 4);
                ldmx4(Af[mt], ad);
            }
            uint32_t Bh[2][4], Bl[2][4];
#pragma unroll
            for (int nt = 0; nt < 2; nt++) {
                const int nrow = wn * 32 + nt * 16 + ((lane >> 4) << 3) + (lane & 7);
                const int kc = k0 + (((lane >> 3) & 1) << 3);
                const int j = kc >> 3;
                const uint32_t bd = sb + TILE_B + nrow * 128 + ((j ^ (nrow & 7)) << 4);
                ldmx4(Bh[nt], bd);
                ldmx4(Bl[nt], bd + TILE_B);
            }
#pragma unroll
            for (int mt = 0; mt < 4; mt++) {
#pragma unroll
                for (int nn = 0; nn < 4; nn++) {
                    const int nt = nn >> 1;
                    const int p = (nn & 1) * 2;
                    mma_fp16(acc[mt][nn], Af[mt], Bh[nt][p], Bh[nt][p + 1]);
                    mma_fp16(acc[mt][nn], Af[mt], Bl[nt][p], Bl[nt][p + 1]);
                }
            }
        }
        __syncthreads();
    }

    // epilogue: all scales already folded into Weff -> write out directly
    const int gm0 = bm * BM + wm * 64;
    const int gn0 = bn * BN + wn * 32;
#pragma unroll
    for (int mt = 0; mt < 4; mt++) {
#pragma unroll
        for (int nn = 0; nn < 4; nn++) {
            const int r0 = gm0 + mt * 16 + (lane >> 2);
            const int c0 = gn0 + nn * 8 + (lane & 3) * 2;
            float2 v0 = make_float2(acc[mt][nn][0], acc[mt][nn][1]);
            float2 v1 = make_float2(acc[mt][nn][2], acc[mt][nn][3]);
            *reinterpret_cast<float2*>(&out[(size_t)r0 * NF + c0]) = v0;
            *reinterpret_cast<float2*>(&out[(size_t)(r0 + 8) * NF + c0]) = v1;
        }
    }
}

// ---------------------------------------------------------------------------
// Launch
// ---------------------------------------------------------------------------
extern "C" void kernel_launch(void* const* d_in, const int* in_sizes, int n_in,
                              void* d_out, int out_size) {
    const float* x      = (const float*)d_in[0];
    const int*   Qidxs  = (const int*)  d_in[1];
    const float* SU     = (const float*)d_in[2];
    const float* SV     = (const float*)d_in[3];
    const float* Wscale = (const float*)d_in[4];
    const float* cb     = (const float*)d_in[5];
    float* out = (float*)d_out;

    conv_x<<<(M_ROWS * (size_t)KF) / (256 * 8), 256>>>(x);
    dequant_fht_row<<<NF / 2, 128>>>(Qidxs, cb, SV, Wscale);
    fht_col1<<<dim3(KF / 256, 64), 256>>>();
    fht_col2<<<dim3(KF / 256, 64), 256>>>(SU);

    cudaFuncSetAttribute(gemm_hmma, cudaFuncAttributeMaxDynamicSharedMemorySize,
                         GEMM_DSMEM);
    gemm_hmma<<<(M_ROWS / BM) * (NF / BN), 256, GEMM_DSMEM>>>(out);
}

// round 6
// speedup vs baseline: 2.9420x; 1.5354x over previous
#include <cuda_runtime.h>
#include <cuda_fp16.h>
#include <cstdint>

// ---------------------------------------------------------------------------
// Problem constants
// ---------------------------------------------------------------------------
#define M_ROWS 8192   // 4*2048 samples
#define NF     4096   // output features
#define KF     4096   // input features

// ---------------------------------------------------------------------------
// Scratch (device globals — no allocation allowed)
// ---------------------------------------------------------------------------
__device__ __half g_Xh[(size_t)M_ROWS * KF];   // x in fp16
__device__ float  g_Wt[(size_t)NF * KF];       // H*W*H intermediate (f32)
__device__ __half g_Wh[(size_t)NF * KF];       // Weff (fp16)

// ---------------------------------------------------------------------------
// Helpers
// ---------------------------------------------------------------------------
__device__ __forceinline__ void fht64(float* v) {
#pragma unroll
    for (int h = 1; h < 64; h <<= 1) {
#pragma unroll
        for (int i = 0; i < 64; i += 2 * h) {
#pragma unroll
            for (int j = i; j < i + h; j++) {
                float a = v[j], b = v[j + h];
                v[j] = a + b;
                v[j + h] = a - b;
            }
        }
    }
}

__device__ __forceinline__ void cp_async16(uint32_t dst_smem, const void* src) {
    asm volatile("cp.async.cg.shared.global [%0], [%1], 16;\n" :: "r"(dst_smem), "l"(src));
}
__device__ __forceinline__ void cp_commit() {
    asm volatile("cp.async.commit_group;\n");
}
template <int N>
__device__ __forceinline__ void cp_wait() {
    asm volatile("cp.async.wait_group %0;\n" :: "n"(N));
}

__device__ __forceinline__ void ldmx4(uint32_t* r, uint32_t addr) {
    asm volatile("ldmatrix.sync.aligned.m8n8.x4.shared.b16 {%0,%1,%2,%3}, [%4];\n"
                 : "=r"(r[0]), "=r"(r[1]), "=r"(r[2]), "=r"(r[3])
                 : "r"(addr));
}

__device__ __forceinline__ void mma_fp16(float* c, const uint32_t* a, uint32_t b0, uint32_t b1) {
    asm volatile(
        "mma.sync.aligned.m16n8k16.row.col.f32.f16.f16.f32 "
        "{%0,%1,%2,%3}, {%4,%5,%6,%7}, {%8,%9}, {%0,%1,%2,%3};\n"
        : "+f"(c[0]), "+f"(c[1]), "+f"(c[2]), "+f"(c[3])
        : "r"(a[0]), "r"(a[1]), "r"(a[2]), "r"(a[3]), "r"(b0), "r"(b1));
}

// ---------------------------------------------------------------------------
// Kernel 1: x -> fp16 (elementwise; both FHTs folded into W)
// ---------------------------------------------------------------------------
__global__ void conv_x(const float* __restrict__ x) {
    const size_t i = ((size_t)blockIdx.x * 256 + threadIdx.x) * 8;
    const float4 a = *reinterpret_cast<const float4*>(x + i);
    const float4 b = *reinterpret_cast<const float4*>(x + i + 4);
    __half2 h0 = __floats2half2_rn(a.x, a.y);
    __half2 h1 = __floats2half2_rn(a.z, a.w);
    __half2 h2 = __floats2half2_rn(b.x, b.y);
    __half2 h3 = __floats2half2_rn(b.z, b.w);
    uint4 pack;
    pack.x = *reinterpret_cast<uint32_t*>(&h0);
    pack.y = *reinterpret_cast<uint32_t*>(&h1);
    pack.z = *reinterpret_cast<uint32_t*>(&h2);
    pack.w = *reinterpret_cast<uint32_t*>(&h3);
    *reinterpret_cast<uint4*>(&g_Xh[i]) = pack;
}

// ---------------------------------------------------------------------------
// Kernel 2: dequant + row-FHT (over k) + SV[k]*Wscale  -> g_Wt (f32)
// ---------------------------------------------------------------------------
__global__ void dequant_fht_row(const int* __restrict__ Q, const float* __restrict__ cb,
                                const float* __restrict__ SV, const float* __restrict__ wsp) {
    __shared__ float s[2][64 * 65];
    const int half_id = threadIdx.x >> 6;
    const int t = threadIdx.x & 63;
    const int n = blockIdx.x * 2 + half_id;
    float* sm = s[half_id];
    const int* q = Q + (size_t)n * 512;

    for (int i = t; i < 4096; i += 64) {
        const int idx = q[i >> 3];
        sm[(i >> 6) * 65 + (i & 63)] = cb[idx * 8 + (i & 7)];
    }
    __syncthreads();

    float v[64];
#pragma unroll
    for (int j = 0; j < 64; j++) v[j] = sm[t * 65 + j];
    fht64(v);
#pragma unroll
    for (int j = 0; j < 64; j++) sm[t * 65 + j] = v[j];
    __syncthreads();

#pragma unroll
    for (int u = 0; u < 64; u++) v[u] = sm[u * 65 + t];
    fht64(v);
#pragma unroll
    for (int u = 0; u < 64; u++) sm[u * 65 + t] = v[u] * (1.0f / 64.0f);
    __syncthreads();

    const float ws = *wsp;
    for (int i = t; i < 4096; i += 64)
        g_Wt[(size_t)n * KF + i] = sm[(i >> 6) * 65 + (i & 63)] * SV[i] * ws;
}

// ---------------------------------------------------------------------------
// Kernel 3: column-FHT pass 1 (over low 6 bits of n), in place on g_Wt.
// ---------------------------------------------------------------------------
__global__ void fht_col1() {
    const int k = blockIdx.x * 256 + threadIdx.x;
    float* base = g_Wt + (size_t)(blockIdx.y * 64) * KF + k;
    float v[64];
#pragma unroll
    for (int r = 0; r < 64; r++) v[r] = base[(size_t)r * KF];
    fht64(v);
#pragma unroll
    for (int r = 0; r < 64; r++) base[(size_t)r * KF] = v[r];
}

// ---------------------------------------------------------------------------
// Kernel 4: column-FHT pass 2 (over high 6 bits of n) + 1/64 + SU[n] -> fp16
// ---------------------------------------------------------------------------
__global__ void fht_col2(const float* __restrict__ SU) {
    const int k = blockIdx.x * 256 + threadIdx.x;
    const int b = blockIdx.y;
    const float* src = g_Wt + (size_t)b * KF + k;
    float v[64];
#pragma unroll
    for (int r = 0; r < 64; r++) v[r] = src[(size_t)r * 64 * KF];
    fht64(v);
#pragma unroll
    for (int r = 0; r < 64; r++) {
        const int n = b + 64 * r;
        const float val = v[r] * (1.0f / 64.0f) * SU[n];
        g_Wh[(size_t)n * KF + k] = __float2half_rn(val);
    }
}

// ---------------------------------------------------------------------------
// Kernel 5: GEMM  out[M, N] = Xh[M, K] @ Wh[N, K]^T  (single-pass fp16)
// 128x128 tile, BK=64, 5-stage cp.async pipeline, XOR-swizzled 128B rows,
// 8 warps (2x4), warp tile 64x32, mma.sync m16n8k16 fp16/f32.
// ---------------------------------------------------------------------------
#define BM 128
#define BN 128
#define BK 64
#define STAGES 5
#define TILE_B 16384                  // one 128x64 fp16 tile = 16 KB
#define STG (2 * TILE_B)              // A + B = 32 KB
#define GEMM_DSMEM (STAGES * STG)     // 160 KB

__global__ __launch_bounds__(256, 1) void gemm_hmma(float* __restrict__ out) {
    extern __shared__ char dyn[];
    const int tid = threadIdx.x;
    const int lane = tid & 31, warp = tid >> 5;
    const int wm = warp & 1, wn = warp >> 1;  // 2 x 4 warp grid

    // block swizzle for L2 reuse: groups of 8 bm-blocks per bn sweep
    const int GM = 8;
    const int NUMN = NF / BN;            // 32
    const int per = GM * NUMN;           // 256
    const int grp = blockIdx.x / per, rem = blockIdx.x % per;
    const int bm = grp * GM + (rem & (GM - 1));
    const int bn = rem / GM;

    const uint32_t sbase = (uint32_t)__cvta_generic_to_shared(dyn);

    float acc[4][4][4];
#pragma unroll
    for (int a = 0; a < 4; a++)
#pragma unroll
        for (int b = 0; b < 4; b++)
#pragma unroll
            for (int c = 0; c < 4; c++) acc[a][b][c] = 0.0f;

    auto load_stage = [&](int st, int c) {
        const uint32_t sb = sbase + st * STG;
        const int k0 = c * BK;
#pragma unroll
        for (int i = 0; i < 4; i++) {
            const int id = tid + i * 256;
            const int r = id >> 3, j = id & 7;
            const uint32_t off = r * 128 + ((j ^ (r & 7)) << 4);
            const size_t ga = (size_t)(bm * BM + r) * KF + k0 + j * 8;
            const size_t gb = (size_t)(bn * BN + r) * KF + k0 + j * 8;
            cp_async16(sb + off,          g_Xh + ga);
            cp_async16(sb + TILE_B + off, g_Wh + gb);
        }
        cp_commit();
    };

    const int NCH = KF / BK;  // 64
    load_stage(0, 0);
    load_stage(1, 1);
    load_stage(2, 2);
    load_stage(3, 3);

    int st_use = 0, st_load = 4;
    for (int c = 0; c < NCH; c++) {
        if (c <= NCH - 5)      cp_wait<3>();
        else if (c == NCH - 4) cp_wait<2>();
        else if (c == NCH - 3) cp_wait<2>();
        else if (c == NCH - 2) cp_wait<1>();
        else                   cp_wait<0>();
        __syncthreads();

        if (c + 4 < NCH) {
            load_stage(st_load, c + 4);
            if (++st_load == STAGES) st_load = 0;
        }

        const uint32_t sb = sbase + st_use * STG;
        if (++st_use == STAGES) st_use = 0;
#pragma unroll
        for (int kk = 0; kk < 4; kk++) {
            const int k0 = kk * 16;
            uint32_t Af[4][4];
#pragma unroll
            for (int mt = 0; mt < 4; mt++) {
                const int row = wm * 64 + mt * 16 + (lane & 15);
                const int ce = k0 + ((lane >> 4) << 3);       // element col
                const int j = ce >> 3;
                const uint32_t ad = sb + row * 128 + ((j ^ (row & 7)) << 4);
                ldmx4(Af[mt], ad);
            }
            uint32_t Bf[2][4];
#pragma unroll
            for (int nt = 0; nt < 2; nt++) {
                const int nrow = wn * 32 + nt * 16 + ((lane >> 4) << 3) + (lane & 7);
                const int kc = k0 + (((lane >> 3) & 1) << 3);
                const int j = kc >> 3;
                const uint32_t bd = sb + TILE_B + nrow * 128 + ((j ^ (nrow & 7)) << 4);
                ldmx4(Bf[nt], bd);
            }
#pragma unroll
            for (int mt = 0; mt < 4; mt++) {
#pragma unroll
                for (int nn = 0; nn < 4; nn++) {
                    const int nt = nn >> 1;
                    const int p = (nn & 1) * 2;
                    mma_fp16(acc[mt][nn], Af[mt], Bf[nt][p], Bf[nt][p + 1]);
                }
            }
        }
        __syncthreads();
    }

    // epilogue: all scales folded into Weff -> write out directly
    const int gm0 = bm * BM + wm * 64;
    const int gn0 = bn * BN + wn * 32;
#pragma unroll
    for (int mt = 0; mt < 4; mt++) {
#pragma unroll
        for (int nn = 0; nn < 4; nn++) {
            const int r0 = gm0 + mt * 16 + (lane >> 2);
            const int c0 = gn0 + nn * 8 + (lane & 3) * 2;
            float2 v0 = make_float2(acc[mt][nn][0], acc[mt][nn][1]);
            float2 v1 = make_float2(acc[mt][nn][2], acc[mt][nn][3]);
            *reinterpret_cast<float2*>(&out[(size_t)r0 * NF + c0]) = v0;
            *reinterpret_cast<float2*>(&out[(size_t)(r0 + 8) * NF + c0]) = v1;
        }
    }
}

// ---------------------------------------------------------------------------
// Launch
// ---------------------------------------------------------------------------
extern "C" void kernel_launch(void* const* d_in, const int* in_sizes, int n_in,
                              void* d_out, int out_size) {
    const float* x      = (const float*)d_in[0];
    const int*   Qidxs  = (const int*)  d_in[1];
    const float* SU     = (const float*)d_in[2];
    const float* SV     = (const float*)d_in[3];
    const float* Wscale = (const float*)d_in[4];
    const float* cb     = (const float*)d_in[5];
    float* out = (float*)d_out;

    conv_x<<<(M_ROWS * (size_t)KF) / (256 * 8), 256>>>(x);
    dequant_fht_row<<<NF / 2, 128>>>(Qidxs, cb, SV, Wscale);
    fht_col1<<<dim3(KF / 256, 64), 256>>>();
    fht_col2<<<dim3(KF / 256, 64), 256>>>(SU);

    cudaFuncSetAttribute(gemm_hmma, cudaFuncAttributeMaxDynamicSharedMemorySize,
                         GEMM_DSMEM);
    gemm_hmma<<<(M_ROWS / BM) * (NF / BN), 256, GEMM_DSMEM>>>(out);
}

// round 16
// speedup vs baseline: 3.3047x; 1.1233x over previous
#include <cuda_runtime.h>
#include <cuda_fp16.h>
#include <cstdint>

// ---------------------------------------------------------------------------
// Problem constants
// ---------------------------------------------------------------------------
#define M_ROWS 8192   // 4*2048 samples
#define NF     4096   // output features
#define KF     4096   // input features

// ---------------------------------------------------------------------------
// Scratch (device globals — no allocation allowed)
// ---------------------------------------------------------------------------
__device__ __half g_Xh[(size_t)M_ROWS * KF];   // x in fp16
__device__ float  g_Wt[(size_t)NF * KF];       // H*W*H intermediate (f32)
__device__ __half g_Wh[(size_t)NF * KF];       // Weff (fp16)

// ---------------------------------------------------------------------------
// Helpers
// ---------------------------------------------------------------------------
__device__ __forceinline__ void fht64(float* v) {
#pragma unroll
    for (int h = 1; h < 64; h <<= 1) {
#pragma unroll
        for (int i = 0; i < 64; i += 2 * h) {
#pragma unroll
            for (int j = i; j < i + h; j++) {
                float a = v[j], b = v[j + h];
                v[j] = a + b;
                v[j + h] = a - b;
            }
        }
    }
}

__device__ __forceinline__ void cp_async16(uint32_t dst_smem, const void* src) {
    asm volatile("cp.async.cg.shared.global [%0], [%1], 16;\n" :: "r"(dst_smem), "l"(src));
}
__device__ __forceinline__ void cp_commit() {
    asm volatile("cp.async.commit_group;\n");
}
template <int N>
__device__ __forceinline__ void cp_wait() {
    asm volatile("cp.async.wait_group %0;\n" :: "n"(N));
}

__device__ __forceinline__ void ldmx4(uint32_t* r, uint32_t addr) {
    asm volatile("ldmatrix.sync.aligned.m8n8.x4.shared.b16 {%0,%1,%2,%3}, [%4];\n"
                 : "=r"(r[0]), "=r"(r[1]), "=r"(r[2]), "=r"(r[3])
                 : "r"(addr));
}

__device__ __forceinline__ void mma_fp16(float* c, const uint32_t* a, uint32_t b0, uint32_t b1) {
    asm volatile(
        "mma.sync.aligned.m16n8k16.row.col.f32.f16.f16.f32 "
        "{%0,%1,%2,%3}, {%4,%5,%6,%7}, {%8,%9}, {%0,%1,%2,%3};\n"
        : "+f"(c[0]), "+f"(c[1]), "+f"(c[2]), "+f"(c[3])
        : "r"(a[0]), "r"(a[1]), "r"(a[2]), "r"(a[3]), "r"(b0), "r"(b1));
}

// ---------------------------------------------------------------------------
// Kernel 1: x -> fp16 (elementwise; both FHTs folded into W)
// ---------------------------------------------------------------------------
__global__ void conv_x(const float* __restrict__ x) {
    const size_t i = ((size_t)blockIdx.x * 256 + threadIdx.x) * 8;
    const float4 a = *reinterpret_cast<const float4*>(x + i);
    const float4 b = *reinterpret_cast<const float4*>(x + i + 4);
    __half2 h0 = __floats2half2_rn(a.x, a.y);
    __half2 h1 = __floats2half2_rn(a.z, a.w);
    __half2 h2 = __floats2half2_rn(b.x, b.y);
    __half2 h3 = __floats2half2_rn(b.z, b.w);
    uint4 pack;
    pack.x = *reinterpret_cast<uint32_t*>(&h0);
    pack.y = *reinterpret_cast<uint32_t*>(&h1);
    pack.z = *reinterpret_cast<uint32_t*>(&h2);
    pack.w = *reinterpret_cast<uint32_t*>(&h3);
    *reinterpret_cast<uint4*>(&g_Xh[i]) = pack;
}

// ---------------------------------------------------------------------------
// Kernel 2: dequant + row-FHT (over k) + SV[k]*Wscale  -> g_Wt (f32)
// ---------------------------------------------------------------------------
__global__ void dequant_fht_row(const int* __restrict__ Q, const float* __restrict__ cb,
                                const float* __restrict__ SV, const float* __restrict__ wsp) {
    __shared__ float s[2][64 * 65];
    const int half_id = threadIdx.x >> 6;
    const int t = threadIdx.x & 63;
    const int n = blockIdx.x * 2 + half_id;
    float* sm = s[half_id];
    const int* q = Q + (size_t)n * 512;

    for (int i = t; i < 4096; i += 64) {
        const int idx = q[i >> 3];
        sm[(i >> 6) * 65 + (i & 63)] = cb[idx * 8 + (i & 7)];
    }
    __syncthreads();

    float v[64];
#pragma unroll
    for (int j = 0; j < 64; j++) v[j] = sm[t * 65 + j];
    fht64(v);
#pragma unroll
    for (int j = 0; j < 64; j++) sm[t * 65 + j] = v[j];
    __syncthreads();

#pragma unroll
    for (int u = 0; u < 64; u++) v[u] = sm[u * 65 + t];
    fht64(v);
#pragma unroll
    for (int u = 0; u < 64; u++) sm[u * 65 + t] = v[u] * (1.0f / 64.0f);
    __syncthreads();

    const float ws = *wsp;
    for (int i = t; i < 4096; i += 64)
        g_Wt[(size_t)n * KF + i] = sm[(i >> 6) * 65 + (i & 63)] * SV[i] * ws;
}

// ---------------------------------------------------------------------------
// Kernel 3: column-FHT pass 1 (over low 6 bits of n), in place on g_Wt.
// ---------------------------------------------------------------------------
__global__ void fht_col1() {
    const int k = blockIdx.x * 256 + threadIdx.x;
    float* base = g_Wt + (size_t)(blockIdx.y * 64) * KF + k;
    float v[64];
#pragma unroll
    for (int r = 0; r < 64; r++) v[r] = base[(size_t)r * KF];
    fht64(v);
#pragma unroll
    for (int r = 0; r < 64; r++) base[(size_t)r * KF] = v[r];
}

// ---------------------------------------------------------------------------
// Kernel 4: column-FHT pass 2 (over high 6 bits of n) + 1/64 + SU[n] -> fp16
// ---------------------------------------------------------------------------
__global__ void fht_col2(const float* __restrict__ SU) {
    const int k = blockIdx.x * 256 + threadIdx.x;
    const int b = blockIdx.y;
    const float* src = g_Wt + (size_t)b * KF + k;
    float v[64];
#pragma unroll
    for (int r = 0; r < 64; r++) v[r] = src[(size_t)r * 64 * KF];
    fht64(v);
#pragma unroll
    for (int r = 0; r < 64; r++) {
        const int n = b + 64 * r;
        const float val = v[r] * (1.0f / 64.0f) * SU[n];
        g_Wh[(size_t)n * KF + k] = __float2half_rn(val);
    }
}

// ---------------------------------------------------------------------------
// Kernel 5: GEMM  out[M, N] = Xh[M, K] @ Wh[N, K]^T  (single-pass fp16)
// CTA tile 128x256, BK=64, 4 stage buffers / 3 groups in flight, XOR-swizzled
// 128B rows, 8 warps (2x4), warp tile 64x64 -> 8 ldmatrix : 32 mma per k16.
// ---------------------------------------------------------------------------
#define BM 128
#define BN 256
#define BK 64
#define STAGES 4
#define TILE_A 16384                  // 128x64 fp16 = 16 KB
#define TILE_BB 32768                 // 256x64 fp16 = 32 KB
#define STG (TILE_A + TILE_BB)        // 48 KB
#define GEMM_DSMEM (STAGES * STG)     // 192 KB

__global__ __launch_bounds__(256, 1) void gemm_hmma(float* __restrict__ out) {
    extern __shared__ char dyn[];
    const int tid = threadIdx.x;
    const int lane = tid & 31, warp = tid >> 5;
    const int wm = warp & 1, wn = warp >> 1;  // 2 x 4 warp grid

    // block swizzle for L2 reuse: groups of 8 bm-blocks per bn sweep
    const int GM = 8;
    const int NUMN = NF / BN;            // 16
    const int per = GM * NUMN;           // 128
    const int grp = blockIdx.x / per, rem = blockIdx.x % per;
    const int bm = grp * GM + (rem & (GM - 1));
    const int bn = rem / GM;

    const uint32_t sbase = (uint32_t)__cvta_generic_to_shared(dyn);

    float acc[4][8][4];
#pragma unroll
    for (int a = 0; a < 4; a++)
#pragma unroll
        for (int b = 0; b < 8; b++)
#pragma unroll
            for (int c = 0; c < 4; c++) acc[a][b][c] = 0.0f;

    auto load_stage = [&](int st, int c) {
        const uint32_t sb = sbase + st * STG;
        const int k0 = c * BK;
#pragma unroll
        for (int i = 0; i < 4; i++) {            // A: 1024 16B chunks
            const int id = tid + i * 256;
            const int r = id >> 3, j = id & 7;
            const uint32_t off = r * 128 + ((j ^ (r & 7)) << 4);
            const size_t ga = (size_t)(bm * BM + r) * KF + k0 + j * 8;
            cp_async16(sb + off, g_Xh + ga);
        }
#pragma unroll
        for (int i = 0; i < 8; i++) {            // B: 2048 16B chunks
            const int id = tid + i * 256;
            const int r = id >> 3, j = id & 7;
            const uint32_t off = r * 128 + ((j ^ (r & 7)) << 4);
            const size_t gb = (size_t)(bn * BN + r) * KF + k0 + j * 8;
            cp_async16(sb + TILE_A + off, g_Wh + gb);
        }
        cp_commit();
    };

    const int NCH = KF / BK;  // 64
    load_stage(0, 0);
    load_stage(1, 1);
    load_stage(2, 2);

    for (int c = 0; c < NCH; c++) {
        // 3 groups in flight max: retire chunk c's group before computing it.
        if (c <= NCH - 3)      cp_wait<2>();
        else if (c == NCH - 2) cp_wait<1>();
        else                   cp_wait<0>();
        __syncthreads();

        if (c + 3 < NCH) load_stage((c + 3) & 3, c + 3);

        const uint32_t sb = sbase + (c & 3) * STG;
#pragma unroll
        for (int kk = 0; kk < 4; kk++) {
            const int k0 = kk * 16;
            uint32_t Af[4][4];
#pragma unroll
            for (int mt = 0; mt < 4; mt++) {
                const int row = wm * 64 + mt * 16 + (lane & 15);
                const int ce = k0 + ((lane >> 4) << 3);       // element col
                const int j = ce >> 3;
                const uint32_t ad = sb + row * 128 + ((j ^ (row & 7)) << 4);
                ldmx4(Af[mt], ad);
            }
            uint32_t Bf[4][4];
#pragma unroll
            for (int nt = 0; nt < 4; nt++) {
                const int nrow = wn * 64 + nt * 16 + ((lane >> 4) << 3) + (lane & 7);
                const int kc = k0 + (((lane >> 3) & 1) << 3);
                const int j = kc >> 3;
                const uint32_t bd = sb + TILE_A + nrow * 128 + ((j ^ (nrow & 7)) << 4);
                ldmx4(Bf[nt], bd);
            }
#pragma unroll
            for (int mt = 0; mt < 4; mt++) {
#pragma unroll
                for (int nn = 0; nn < 8; nn++) {
                    const int nt = nn >> 1;
                    const int p = (nn & 1) * 2;
                    mma_fp16(acc[mt][nn], Af[mt], Bf[nt][p], Bf[nt][p + 1]);
                }
            }
        }
        __syncthreads();
    }

    // epilogue: all scales folded into Weff -> write out directly
    const int gm0 = bm * BM + wm * 64;
    const int gn0 = bn * BN + wn * 64;
#pragma unroll
    for (int mt = 0; mt < 4; mt++) {
#pragma unroll
        for (int nn = 0; nn < 8; nn++) {
            const int r0 = gm0 + mt * 16 + (lane >> 2);
            const int c0 = gn0 + nn * 8 + (lane & 3) * 2;
            float2 v0 = make_float2(acc[mt][nn][0], acc[mt][nn][1]);
            float2 v1 = make_float2(acc[mt][nn][2], acc[mt][nn][3]);
            *reinterpret_cast<float2*>(&out[(size_t)r0 * NF + c0]) = v0;
            *reinterpret_cast<float2*>(&out[(size_t)(r0 + 8) * NF + c0]) = v1;
        }
    }
}

// ---------------------------------------------------------------------------
// Launch
// ---------------------------------------------------------------------------
extern "C" void kernel_launch(void* const* d_in, const int* in_sizes, int n_in,
                              void* d_out, int out_size) {
    const float* x      = (const float*)d_in[0];
    const int*   Qidxs  = (const int*)  d_in[1];
    const float* SU     = (const float*)d_in[2];
    const float* SV     = (const float*)d_in[3];
    const float* Wscale = (const float*)d_in[4];
    const float* cb     = (const float*)d_in[5];
    float* out = (float*)d_out;

    conv_x<<<(M_ROWS * (size_t)KF) / (256 * 8), 256>>>(x);
    dequant_fht_row<<<NF / 2, 128>>>(Qidxs, cb, SV, Wscale);
    fht_col1<<<dim3(KF / 256, 64), 256>>>();
    fht_col2<<<dim3(KF / 256, 64), 256>>>(SU);

    cudaFuncSetAttribute(gemm_hmma, cudaFuncAttributeMaxDynamicSharedMemorySize,
                         GEMM_DSMEM);
    gemm_hmma<<<(M_ROWS / BM) * (NF / BN), 256, GEMM_DSMEM>>>(out);
}